// round 8
// baseline (speedup 1.0000x reference)
#include <cuda_runtime.h>
#include <cstdint>

#define B_   64
#define N_   128
#define F_   128
#define R_   64
#define H_   256
#define L_   3
#define ROWS (B_*N_)

// image sizes in words
#define CFW 8704    // [64][136]
#define DFW 4608    // [64][72]
#define FCW 9216    // [128][72]
#define XSW 8704    // [64][136]
#define DSW 4608    // [64][72]

__device__ float4 g_cf[12 * CFW / 4];
__device__ float4 g_df[12 * DFW / 4];
__device__ float4 g_fc[12 * FCW / 4];
__device__ float4 g_xs[128 * XSW / 4];
__device__ float4 g_ds[128 * DSW / 4];
__device__ float g_v[F_];

__device__ __forceinline__ uint32_t f2tf(float x) {
    uint32_t r; asm("cvt.rna.tf32.f32 %0, %1;" : "=r"(r) : "f"(x)); return r;
}
__device__ __forceinline__ float tanh_fast(float x) {
    float r; asm("tanh.approx.f32 %0, %1;" : "=f"(r) : "f"(x)); return r;
}
__device__ __forceinline__ int pk(int k) {           // packed octet permutation
    return (k & ~7) + 2 * (k & 3) + ((k >> 2) & 1);
}
__device__ __forceinline__ void mma8(float* d, uint32_t a0, uint32_t a1, uint32_t a2, uint32_t a3,
                                     uint32_t b0, uint32_t b1) {
    asm volatile(
        "mma.sync.aligned.m16n8k8.row.col.f32.tf32.tf32.f32 "
        "{%0,%1,%2,%3},{%4,%5,%6,%7},{%8,%9},{%0,%1,%2,%3};"
        : "+f"(d[0]), "+f"(d[1]), "+f"(d[2]), "+f"(d[3])
        : "r"(a0), "r"(a1), "r"(a2), "r"(a3), "r"(b0), "r"(b1));
}
__device__ __forceinline__ void cpa16(uint32_t dst, const float4* src) {
    asm volatile("cp.async.ca.shared.global [%0], [%1], 16;" :: "r"(dst), "l"(src));
}
#define CP_COMMIT() asm volatile("cp.async.commit_group;" ::: "memory")
template<int N>
__device__ __forceinline__ void cp_wait() {
    asm volatile("cp.async.wait_group %0;" :: "n"(N) : "memory");
}
template<int NC>
__device__ __forceinline__ void copy_img(uint32_t dst, const float4* __restrict__ src, int tid) {
    #pragma unroll
    for (int i = tid; i < NC; i += 256) cpa16(dst + i * 16, src + i);
}
__device__ __forceinline__ uint32_t smem_u32(const void* p) {
    uint32_t a;
    asm("{ .reg .u64 t; cvta.to.shared.u64 t, %1; cvt.u32.u64 %0, t; }" : "=r"(a) : "l"(p));
    return a;
}

// ---------------- Kernel 0: prep — pack weights/x to tf32 smem-images; fold head ----------------
__global__ void prep_kernel(const float* __restrict__ x,
                            const float* __restrict__ Wcf_w, const float* __restrict__ Wdf_w,
                            const float* __restrict__ Wfc_w,
                            const float* __restrict__ fc0_w, const float* __restrict__ fc0_b,
                            const float* __restrict__ out_w, const float* __restrict__ out_b,
                            float* __restrict__ out) {
    int bid = blockIdx.x, tid = threadIdx.x;
    if (bid < 128) {                       // x tile images
        float* dst = (float*)g_xs + bid * XSW;
        const float* src = x + (size_t)bid * 64 * 128;
        for (int idx = tid; idx < 64 * 128; idx += 256) {
            int row = idx >> 7, k = idx & 127;
            dst[row * 136 + pk(k)] = __uint_as_float(f2tf(src[idx]));
        }
    } else if (bid < 140) {                // weight chunk images
        int wi = bid - 128, l = wi >> 2, c = wi & 3;
        float* dcf = (float*)g_cf + wi * CFW;
        const float* scf = Wcf_w + (size_t)l * 32768 + c * 64 * 128;
        for (int idx = tid; idx < 64 * 128; idx += 256) {
            int row = idx >> 7, k = idx & 127;
            dcf[row * 136 + pk(k)] = __uint_as_float(f2tf(scf[idx]));
        }
        float* ddf = (float*)g_df + wi * DFW;
        const float* sdf = Wdf_w + (size_t)l * 16384 + c * 64 * 64;
        for (int idx = tid; idx < 64 * 64; idx += 256) {
            int row = idx >> 6, k = idx & 63;
            ddf[row * 72 + pk(k)] = __uint_as_float(f2tf(sdf[idx]));
        }
        float* dfc = (float*)g_fc + wi * FCW;
        const float* sfc = Wfc_w + (size_t)l * 32768 + c * 64;
        for (int idx = tid; idx < 128 * 64; idx += 256) {
            int row = idx >> 6, k = idx & 63;
            dfc[row * 72 + pk(k)] = __uint_as_float(f2tf(sfc[row * 256 + k]));
        }
    } else {                               // fold head + init out
        if (tid < 128) {
            float a = 0.f;
            #pragma unroll 8
            for (int c = 0; c < 256; c++) a += out_w[c] * fc0_w[c * F_ + tid];
            g_v[tid] = a;
        }
        __shared__ float cs;
        if (tid == 0) {
            float s = out_b[0];
            for (int c = 0; c < 256; c++) s += out_w[c] * fc0_b[c];
            cs = s;
        }
        __syncthreads();
        if (tid < B_) out[tid] = cs;
    }
}

// ---------------- Kernel A: d_sum row reduction -> packed Ds images ----------------
__global__ void reduce_dist_kernel(const float* __restrict__ dist) {
    int row = blockIdx.x;
    int tid = threadIdx.x;
    const float4* p = (const float4*)(dist + (size_t)row * (N_ * R_));
    float4 acc = make_float4(0.f, 0.f, 0.f, 0.f);
    #pragma unroll
    for (int t = 0; t < 8; t++) {
        float4 v = __ldcs(&p[tid + t * 256]);
        acc.x += v.x; acc.y += v.y; acc.z += v.z; acc.w += v.w;
    }
    __shared__ float4 s[256];
    s[tid] = acc;
    __syncthreads();
    if (tid < 16) {
        float4 a = s[tid];
        #pragma unroll
        for (int m = 1; m < 16; m++) {
            float4 b = s[tid + 16 * m];
            a.x += b.x; a.y += b.y; a.z += b.z; a.w += b.w;
        }
        int c4 = tid * 4;
        float* dp = (float*)g_ds + (row >> 6) * DSW + (row & 63) * 72
                    + (c4 & ~7) + ((c4 & 4) ? 1 : 0);
        dp[0] = __uint_as_float(f2tf(a.x));
        dp[2] = __uint_as_float(f2tf(a.y));
        dp[4] = __uint_as_float(f2tf(a.z));
        dp[6] = __uint_as_float(f2tf(a.w));
    }
}

// ---------------- Kernel B: mma.sync tf32 fused 3 layers + pooling ----------------
// 128 CTAs x 64 rows, 256 threads. smem word offsets:
enum {
    OXS  = 0,                    // Xs  [64][136]
    ODS  = OXS + XSW,            // Ds  [64][72]
    OPB  = ODS + DSW,            // Pb  [64][72]
    OCF0 = OPB + 4608,
    OCF1 = OCF0 + CFW,
    ODF0 = OCF1 + CFW,
    ODF1 = ODF0 + DFW,
    OFC  = ODF1 + DFW,
    OBC  = OFC + FCW,            // bcf [256]
    OBD  = OBC + 256,            // 128*bdf [256]
    OVV  = OBD + 256,            // v [128]
    ORD  = OVV + 128,            // reduce [256]
    TOTW = ORD + 256
};
#define SMEMB (TOTW * 4)

__global__ __launch_bounds__(256, 1)
void dtnn_mma_kernel(const float* __restrict__ Wcf_b, const float* __restrict__ Wdf_b,
                     float* __restrict__ out) {
    extern __shared__ float sm[];
    float* Xs = sm + OXS; float* Ds = sm + ODS; float* Pb = sm + OPB;
    float* CFs[2] = { sm + OCF0, sm + OCF1 };
    float* DFs[2] = { sm + ODF0, sm + ODF1 };
    float* FCb = sm + OFC;
    float* bc = sm + OBC; float* bd = sm + OBD;
    float* vv = sm + OVV; float* rd = sm + ORD;
    uint32_t sb = smem_u32(sm);
    uint32_t* Xu = (uint32_t*)Xs;
    uint32_t* Pu = (uint32_t*)Pb;

    int tid = threadIdx.x, lane = tid & 31, w = tid >> 5;
    int g = lane >> 2, t = lane & 3;
    int wm = w & 1, wn = w >> 1;          // warp grid: 2 (M) x 4 (N)
    int pe = (t < 2) ? 4 * t : 4 * t - 7; // packed pos of even col 2t; odd at +2
    int bid = blockIdx.x;

    // pre-loop async loads: Xs, Ds, CF[0], DF[0]
    copy_img<XSW/4>(sb + OXS * 4, g_xs + bid * (XSW/4), tid);
    copy_img<DSW/4>(sb + ODS * 4, g_ds + bid * (DSW/4), tid);
    copy_img<CFW/4>(sb + OCF0 * 4, g_cf, tid);
    copy_img<DFW/4>(sb + ODF0 * 4, g_df, tid);
    CP_COMMIT();
    bc[tid] = Wcf_b[tid];
    bd[tid] = 128.f * Wdf_b[tid];
    if (tid < 128) vv[tid] = g_v[tid];
    cp_wait<0>();
    __syncthreads();

    float hacc[2][4][4] = {};
    float pool = 0.f;

    for (int i = 0; i < 12; i++) {
        int l = i >> 2, c = i & 3, buf = i & 1;

        // issue FC[i]; then CF/DF[i+1] into alternate buffers
        copy_img<FCW/4>(sb + OFC * 4, g_fc + i * (FCW/4), tid);
        CP_COMMIT();
        if (i < 11) {
            uint32_t cfo = (buf ? OCF0 : OCF1) * 4;
            uint32_t dfo = (buf ? ODF0 : ODF1) * 4;
            copy_img<CFW/4>(sb + cfo, g_cf + (i + 1) * (CFW/4), tid);
            copy_img<DFW/4>(sb + dfo, g_df + (i + 1) * (DFW/4), tid);
            CP_COMMIT();
        }

        float* CF = CFs[buf];
        float* DF = DFs[buf];
        float cf[2][2][4] = {}, df[2][2][4] = {};
        // cf: Xs[64x128] @ CF^T (warp tile 32x16)
        #pragma unroll
        for (int ks = 0; ks < 16; ks++) {
            int k8 = ks * 8 + 2 * t;
            uint2 A0 = *(const uint2*)(Xs + (wm * 32 + g) * 136 + k8);
            uint2 A1 = *(const uint2*)(Xs + (wm * 32 + 8 + g) * 136 + k8);
            uint2 A2 = *(const uint2*)(Xs + (wm * 32 + 16 + g) * 136 + k8);
            uint2 A3 = *(const uint2*)(Xs + (wm * 32 + 24 + g) * 136 + k8);
            #pragma unroll
            for (int nt = 0; nt < 2; nt++) {
                uint2 Bv = *(const uint2*)(CF + (wn * 16 + nt * 8 + g) * 136 + k8);
                mma8(cf[0][nt], A0.x, A1.x, A0.y, A1.y, Bv.x, Bv.y);
                mma8(cf[1][nt], A2.x, A3.x, A2.y, A3.y, Bv.x, Bv.y);
            }
        }
        // df: Ds[64x64] @ DF^T
        #pragma unroll
        for (int ks = 0; ks < 8; ks++) {
            int k8 = ks * 8 + 2 * t;
            uint2 A0 = *(const uint2*)(Ds + (wm * 32 + g) * 72 + k8);
            uint2 A1 = *(const uint2*)(Ds + (wm * 32 + 8 + g) * 72 + k8);
            uint2 A2 = *(const uint2*)(Ds + (wm * 32 + 16 + g) * 72 + k8);
            uint2 A3 = *(const uint2*)(Ds + (wm * 32 + 24 + g) * 72 + k8);
            #pragma unroll
            for (int nt = 0; nt < 2; nt++) {
                uint2 Bv = *(const uint2*)(DF + (wn * 16 + nt * 8 + g) * 72 + k8);
                mma8(df[0][nt], A0.x, A1.x, A0.y, A1.y, Bv.x, Bv.y);
                mma8(df[1][nt], A2.x, A3.x, A2.y, A3.y, Bv.x, Bv.y);
            }
        }
        // P = (cf+bc)*(df+128*bd) -> Pb (packed tf32)
        int hc = c * 64;
        #pragma unroll
        for (int mt = 0; mt < 2; mt++)
        #pragma unroll
        for (int nt = 0; nt < 2; nt++) {
            int o = wn * 16 + nt * 8;
            int col = o + 2 * t;
            int row = wm * 32 + mt * 16 + g;
            float b0c = bc[hc + col], b1c = bc[hc + col + 1];
            float b0d = bd[hc + col], b1d = bd[hc + col + 1];
            float* f4 = cf[mt][nt];
            float* d4 = df[mt][nt];
            int a0 = row * 72 + o + pe;
            int a1 = (row + 8) * 72 + o + pe;
            Pu[a0]     = f2tf((f4[0] + b0c) * (d4[0] + b0d));
            Pu[a0 + 2] = f2tf((f4[1] + b1c) * (d4[1] + b1d));
            Pu[a1]     = f2tf((f4[2] + b0c) * (d4[2] + b0d));
            Pu[a1 + 2] = f2tf((f4[3] + b1c) * (d4[3] + b1d));
        }

        if (i < 11) cp_wait<1>(); else cp_wait<0>();   // FC[i] arrived
        __syncthreads();                                // Pb + FCb ready

        // fc: Pb[64x64] @ FCb^T accumulate (warp tile 32x32)
        #pragma unroll
        for (int ks = 0; ks < 8; ks++) {
            int k8 = ks * 8 + 2 * t;
            uint2 A0 = *(const uint2*)(Pb + (wm * 32 + g) * 72 + k8);
            uint2 A1 = *(const uint2*)(Pb + (wm * 32 + 8 + g) * 72 + k8);
            uint2 A2 = *(const uint2*)(Pb + (wm * 32 + 16 + g) * 72 + k8);
            uint2 A3 = *(const uint2*)(Pb + (wm * 32 + 24 + g) * 72 + k8);
            #pragma unroll
            for (int nt = 0; nt < 4; nt++) {
                uint2 Bv = *(const uint2*)(FCb + (wn * 32 + nt * 8 + g) * 72 + k8);
                mma8(hacc[0][nt], A0.x, A1.x, A0.y, A1.y, Bv.x, Bv.y);
                mma8(hacc[1][nt], A2.x, A3.x, A2.y, A3.y, Bv.x, Bv.y);
            }
        }

        if (c == 3) {
            if (l < 2) {
                // x = h + tanh(h) -> Xs (packed); next layer biases
                #pragma unroll
                for (int mt = 0; mt < 2; mt++)
                #pragma unroll
                for (int nt = 0; nt < 4; nt++) {
                    int o = wn * 32 + nt * 8;
                    int row = wm * 32 + mt * 16 + g;
                    float* h4 = hacc[mt][nt];
                    int a0 = row * 136 + o + pe;
                    int a1 = (row + 8) * 136 + o + pe;
                    Xu[a0]     = f2tf(h4[0] + tanh_fast(h4[0]));
                    Xu[a0 + 2] = f2tf(h4[1] + tanh_fast(h4[1]));
                    Xu[a1]     = f2tf(h4[2] + tanh_fast(h4[2]));
                    Xu[a1 + 2] = f2tf(h4[3] + tanh_fast(h4[3]));
                }
                bc[tid] = Wcf_b[(l + 1) * H_ + tid];
                bd[tid] = 128.f * Wdf_b[(l + 1) * H_ + tid];
                #pragma unroll
                for (int mt = 0; mt < 2; mt++)
                #pragma unroll
                for (int nt = 0; nt < 4; nt++)
                #pragma unroll
                for (int e = 0; e < 4; e++) hacc[mt][nt][e] = 0.f;
            } else {
                #pragma unroll
                for (int mt = 0; mt < 2; mt++)
                #pragma unroll
                for (int nt = 0; nt < 4; nt++) {
                    int col = wn * 32 + nt * 8 + 2 * t;
                    float* h4 = hacc[mt][nt];
                    pool += (h4[0] + tanh_fast(h4[0])) * vv[col];
                    pool += (h4[1] + tanh_fast(h4[1])) * vv[col + 1];
                    pool += (h4[2] + tanh_fast(h4[2])) * vv[col];
                    pool += (h4[3] + tanh_fast(h4[3])) * vv[col + 1];
                }
                rd[tid] = pool;
                __syncthreads();
                for (int s = 128; s > 0; s >>= 1) {
                    if (tid < s) rd[tid] += rd[tid + s];
                    __syncthreads();
                }
                if (tid == 0) atomicAdd(out + (blockIdx.x >> 1), rd[0]);
            }
        }
        if (i < 11) { __syncthreads(); }   // ensure CF/DF[i+1] wait point is collective
    }
}

// ---------------- launch ----------------
extern "C" void kernel_launch(void* const* d_in, const int* in_sizes, int n_in,
                              void* d_out, int out_size) {
    const float* x     = (const float*)d_in[0];
    const float* dist  = (const float*)d_in[1];
    const float* Wcf_w = (const float*)d_in[2];
    const float* Wcf_b = (const float*)d_in[3];
    const float* Wdf_w = (const float*)d_in[4];
    const float* Wdf_b = (const float*)d_in[5];
    const float* Wfc_w = (const float*)d_in[6];
    const float* fc0_w = (const float*)d_in[7];
    const float* fc0_b = (const float*)d_in[8];
    const float* out_w = (const float*)d_in[9];
    const float* out_b = (const float*)d_in[10];
    float* out = (float*)d_out;

    cudaFuncSetAttribute(dtnn_mma_kernel,
                         cudaFuncAttributeMaxDynamicSharedMemorySize, SMEMB);

    prep_kernel<<<141, 256>>>(x, Wcf_w, Wdf_w, Wfc_w, fc0_w, fc0_b, out_w, out_b, out);
    reduce_dist_kernel<<<ROWS, 256>>>(dist);
    dtnn_mma_kernel<<<128, 256, SMEMB>>>(Wcf_b, Wdf_b, out);
}

// round 9
// speedup vs baseline: 1.1333x; 1.1333x over previous
#include <cuda_runtime.h>
#include <cstdint>

#define B_   64
#define N_   128
#define F_   128
#define R_   64
#define H_   256
#define L_   3
#define ROWS (B_*N_)

// image sizes in words
#define CFW 8704    // [64][136]
#define DFW 4608    // [64][72]
#define FCW 9216    // [128][72]
#define XSW 8704    // [64][136]
#define DSW 4608    // [64][72]

__device__ float4 g_cf[12 * CFW / 4];
__device__ float4 g_df[12 * DFW / 4];
__device__ float4 g_fc[12 * FCW / 4];
__device__ float4 g_xs[128 * XSW / 4];
__device__ float4 g_ds[128 * DSW / 4];
__device__ float g_v[F_];

__device__ __forceinline__ uint32_t f2tf(float x) {
    uint32_t r; asm("cvt.rna.tf32.f32 %0, %1;" : "=r"(r) : "f"(x)); return r;
}
__device__ __forceinline__ float tanh_fast(float x) {
    float r; asm("tanh.approx.f32 %0, %1;" : "=f"(r) : "f"(x)); return r;
}
__device__ __forceinline__ void mma8(float* d, uint32_t a0, uint32_t a1, uint32_t a2, uint32_t a3,
                                     uint32_t b0, uint32_t b1) {
    asm volatile(
        "mma.sync.aligned.m16n8k8.row.col.f32.tf32.tf32.f32 "
        "{%0,%1,%2,%3},{%4,%5,%6,%7},{%8,%9},{%0,%1,%2,%3};"
        : "+f"(d[0]), "+f"(d[1]), "+f"(d[2]), "+f"(d[3])
        : "r"(a0), "r"(a1), "r"(a2), "r"(a3), "r"(b0), "r"(b1));
}
__device__ __forceinline__ void cpa16(uint32_t dst, const float4* src) {
    asm volatile("cp.async.ca.shared.global [%0], [%1], 16;" :: "r"(dst), "l"(src));
}
#define CP_COMMIT() asm volatile("cp.async.commit_group;" ::: "memory")
template<int N>
__device__ __forceinline__ void cp_wait() {
    asm volatile("cp.async.wait_group %0;" :: "n"(N) : "memory");
}
template<int NC>
__device__ __forceinline__ void copy_img(uint32_t dst, const float4* __restrict__ src, int tid) {
    #pragma unroll
    for (int i = tid; i < NC; i += 256) cpa16(dst + i * 16, src + i);
}
__device__ __forceinline__ uint32_t smem_u32(const void* p) {
    uint32_t a;
    asm("{ .reg .u64 t; cvta.to.shared.u64 t, %1; cvt.u32.u64 %0, t; }" : "=r"(a) : "l"(p));
    return a;
}

// Octet pack: out[0..7] = in[0,4,1,5,2,6,3,7], tf32-rounded. 2x float4 in/out.
__device__ __forceinline__ void pack_oct(float* dst, const float* __restrict__ src) {
    float4 a = *(const float4*)src;
    float4 b = *(const float4*)(src + 4);
    uint4 o1, o2;
    o1.x = f2tf(a.x); o1.y = f2tf(b.x); o1.z = f2tf(a.y); o1.w = f2tf(b.y);
    o2.x = f2tf(a.z); o2.y = f2tf(b.z); o2.z = f2tf(a.w); o2.w = f2tf(b.w);
    *(uint4*)dst = o1;
    *(uint4*)(dst + 4) = o2;
}

// ---------------- Kernel A: prep (141 blocks, first) + reduce (8192 blocks) ----------------
__global__ void prep_reduce_kernel(const float* __restrict__ dist, const float* __restrict__ x,
                                   const float* __restrict__ Wcf_w, const float* __restrict__ Wdf_w,
                                   const float* __restrict__ Wfc_w,
                                   const float* __restrict__ fc0_w, const float* __restrict__ fc0_b,
                                   const float* __restrict__ out_w, const float* __restrict__ out_b,
                                   float* __restrict__ out) {
    int bid = blockIdx.x, tid = threadIdx.x;
    if (bid >= 141) {                      // ---- streaming reduction ----
        int row = bid - 141;
        const float4* p = (const float4*)(dist + (size_t)row * (N_ * R_));
        float4 acc = make_float4(0.f, 0.f, 0.f, 0.f);
        #pragma unroll
        for (int t = 0; t < 8; t++) {
            float4 v = __ldcs(&p[tid + t * 256]);
            acc.x += v.x; acc.y += v.y; acc.z += v.z; acc.w += v.w;
        }
        __shared__ float4 s[256];
        s[tid] = acc;
        __syncthreads();
        if (tid < 16) {
            float4 a = s[tid];
            #pragma unroll
            for (int m = 1; m < 16; m++) {
                float4 b = s[tid + 16 * m];
                a.x += b.x; a.y += b.y; a.z += b.z; a.w += b.w;
            }
            int c4 = tid * 4;
            float* dp = (float*)g_ds + (row >> 6) * DSW + (row & 63) * 72
                        + (c4 & ~7) + ((c4 & 4) ? 1 : 0);
            dp[0] = __uint_as_float(f2tf(a.x));
            dp[2] = __uint_as_float(f2tf(a.y));
            dp[4] = __uint_as_float(f2tf(a.z));
            dp[6] = __uint_as_float(f2tf(a.w));
        }
    } else if (bid < 128) {                // ---- x tile images: 1024 octets ----
        float* dst = (float*)g_xs + bid * XSW;
        const float* src = x + (size_t)bid * 64 * 128;
        #pragma unroll
        for (int i = 0; i < 4; i++) {
            int oct = tid + i * 256;
            int row = oct >> 4, ko = oct & 15;
            pack_oct(dst + row * 136 + ko * 8, src + row * 128 + ko * 8);
        }
    } else if (bid < 140) {                // ---- weight chunk images ----
        int wi = bid - 128, l = wi >> 2, c = wi & 3;
        float* dcf = (float*)g_cf + wi * CFW;
        const float* scf = Wcf_w + (size_t)l * 32768 + c * 8192;
        #pragma unroll
        for (int i = 0; i < 4; i++) {      // 1024 octets
            int oct = tid + i * 256;
            int row = oct >> 4, ko = oct & 15;
            pack_oct(dcf + row * 136 + ko * 8, scf + row * 128 + ko * 8);
        }
        float* ddf = (float*)g_df + wi * DFW;
        const float* sdf = Wdf_w + (size_t)l * 16384 + c * 4096;
        #pragma unroll
        for (int i = 0; i < 2; i++) {      // 512 octets
            int oct = tid + i * 256;
            int row = oct >> 3, ko = oct & 7;
            pack_oct(ddf + row * 72 + ko * 8, sdf + row * 64 + ko * 8);
        }
        float* dfc = (float*)g_fc + wi * FCW;
        const float* sfc = Wfc_w + (size_t)l * 32768 + c * 64;
        #pragma unroll
        for (int i = 0; i < 4; i++) {      // 1024 octets
            int oct = tid + i * 256;
            int row = oct >> 3, ko = oct & 7;
            pack_oct(dfc + row * 72 + ko * 8, sfc + row * 256 + ko * 8);
        }
    } else {                               // ---- fold head + init out ----
        if (tid < 128) {
            float a = 0.f;
            #pragma unroll 8
            for (int c = 0; c < 256; c++) a += out_w[c] * fc0_w[c * F_ + tid];
            g_v[tid] = a;
        }
        __shared__ float cs;
        if (tid == 0) {
            float s = out_b[0];
            for (int c = 0; c < 256; c++) s += out_w[c] * fc0_b[c];
            cs = s;
        }
        __syncthreads();
        if (tid < B_) out[tid] = cs;
    }
}

// ---------------- Kernel B: mma.sync tf32 fused 3 layers + pooling ----------------
enum {
    OXS  = 0,
    ODS  = OXS + XSW,
    OPB  = ODS + DSW,
    OCF0 = OPB + 4608,
    OCF1 = OCF0 + CFW,
    ODF0 = OCF1 + CFW,
    ODF1 = ODF0 + DFW,
    OFC  = ODF1 + DFW,
    OBC  = OFC + FCW,
    OBD  = OBC + 256,
    OVV  = OBD + 256,
    ORD  = OVV + 128,
    TOTW = ORD + 256
};
#define SMEMB (TOTW * 4)

__global__ __launch_bounds__(256, 1)
void dtnn_mma_kernel(const float* __restrict__ Wcf_b, const float* __restrict__ Wdf_b,
                     float* __restrict__ out) {
    extern __shared__ float sm[];
    float* Xs = sm + OXS; float* Ds = sm + ODS; float* Pb = sm + OPB;
    float* CFs[2] = { sm + OCF0, sm + OCF1 };
    float* DFs[2] = { sm + ODF0, sm + ODF1 };
    float* FCb = sm + OFC;
    float* bc = sm + OBC; float* bd = sm + OBD;
    float* vv = sm + OVV; float* rd = sm + ORD;
    uint32_t sb = smem_u32(sm);
    uint32_t* Xu = (uint32_t*)Xs;
    uint32_t* Pu = (uint32_t*)Pb;

    int tid = threadIdx.x, lane = tid & 31, w = tid >> 5;
    int g = lane >> 2, t = lane & 3;
    int wm = w & 1, wn = w >> 1;
    int pe = (t < 2) ? 4 * t : 4 * t - 7;
    int bid = blockIdx.x;

    copy_img<XSW/4>(sb + OXS * 4, g_xs + bid * (XSW/4), tid);
    copy_img<DSW/4>(sb + ODS * 4, g_ds + bid * (DSW/4), tid);
    copy_img<CFW/4>(sb + OCF0 * 4, g_cf, tid);
    copy_img<DFW/4>(sb + ODF0 * 4, g_df, tid);
    CP_COMMIT();
    bc[tid] = Wcf_b[tid];
    bd[tid] = 128.f * Wdf_b[tid];
    if (tid < 128) vv[tid] = g_v[tid];
    cp_wait<0>();
    __syncthreads();

    float hacc[2][4][4] = {};
    float pool = 0.f;

    for (int i = 0; i < 12; i++) {
        int l = i >> 2, c = i & 3, buf = i & 1;

        copy_img<FCW/4>(sb + OFC * 4, g_fc + i * (FCW/4), tid);
        CP_COMMIT();
        if (i < 11) {
            uint32_t cfo = (buf ? OCF0 : OCF1) * 4;
            uint32_t dfo = (buf ? ODF0 : ODF1) * 4;
            copy_img<CFW/4>(sb + cfo, g_cf + (i + 1) * (CFW/4), tid);
            copy_img<DFW/4>(sb + dfo, g_df + (i + 1) * (DFW/4), tid);
            CP_COMMIT();
        }

        float* CF = CFs[buf];
        float* DF = DFs[buf];
        float cf[2][2][4] = {}, df[2][2][4] = {};
        #pragma unroll
        for (int ks = 0; ks < 16; ks++) {
            int k8 = ks * 8 + 2 * t;
            uint2 A0 = *(const uint2*)(Xs + (wm * 32 + g) * 136 + k8);
            uint2 A1 = *(const uint2*)(Xs + (wm * 32 + 8 + g) * 136 + k8);
            uint2 A2 = *(const uint2*)(Xs + (wm * 32 + 16 + g) * 136 + k8);
            uint2 A3 = *(const uint2*)(Xs + (wm * 32 + 24 + g) * 136 + k8);
            #pragma unroll
            for (int nt = 0; nt < 2; nt++) {
                uint2 Bv = *(const uint2*)(CF + (wn * 16 + nt * 8 + g) * 136 + k8);
                mma8(cf[0][nt], A0.x, A1.x, A0.y, A1.y, Bv.x, Bv.y);
                mma8(cf[1][nt], A2.x, A3.x, A2.y, A3.y, Bv.x, Bv.y);
            }
        }
        #pragma unroll
        for (int ks = 0; ks < 8; ks++) {
            int k8 = ks * 8 + 2 * t;
            uint2 A0 = *(const uint2*)(Ds + (wm * 32 + g) * 72 + k8);
            uint2 A1 = *(const uint2*)(Ds + (wm * 32 + 8 + g) * 72 + k8);
            uint2 A2 = *(const uint2*)(Ds + (wm * 32 + 16 + g) * 72 + k8);
            uint2 A3 = *(const uint2*)(Ds + (wm * 32 + 24 + g) * 72 + k8);
            #pragma unroll
            for (int nt = 0; nt < 2; nt++) {
                uint2 Bv = *(const uint2*)(DF + (wn * 16 + nt * 8 + g) * 72 + k8);
                mma8(df[0][nt], A0.x, A1.x, A0.y, A1.y, Bv.x, Bv.y);
                mma8(df[1][nt], A2.x, A3.x, A2.y, A3.y, Bv.x, Bv.y);
            }
        }
        int hc = c * 64;
        #pragma unroll
        for (int mt = 0; mt < 2; mt++)
        #pragma unroll
        for (int nt = 0; nt < 2; nt++) {
            int o = wn * 16 + nt * 8;
            int col = o + 2 * t;
            int row = wm * 32 + mt * 16 + g;
            float b0c = bc[hc + col], b1c = bc[hc + col + 1];
            float b0d = bd[hc + col], b1d = bd[hc + col + 1];
            float* f4 = cf[mt][nt];
            float* d4 = df[mt][nt];
            int a0 = row * 72 + o + pe;
            int a1 = (row + 8) * 72 + o + pe;
            Pu[a0]     = f2tf((f4[0] + b0c) * (d4[0] + b0d));
            Pu[a0 + 2] = f2tf((f4[1] + b1c) * (d4[1] + b1d));
            Pu[a1]     = f2tf((f4[2] + b0c) * (d4[2] + b0d));
            Pu[a1 + 2] = f2tf((f4[3] + b1c) * (d4[3] + b1d));
        }

        if (i < 11) cp_wait<1>(); else cp_wait<0>();
        __syncthreads();

        #pragma unroll
        for (int ks = 0; ks < 8; ks++) {
            int k8 = ks * 8 + 2 * t;
            uint2 A0 = *(const uint2*)(Pb + (wm * 32 + g) * 72 + k8);
            uint2 A1 = *(const uint2*)(Pb + (wm * 32 + 8 + g) * 72 + k8);
            uint2 A2 = *(const uint2*)(Pb + (wm * 32 + 16 + g) * 72 + k8);
            uint2 A3 = *(const uint2*)(Pb + (wm * 32 + 24 + g) * 72 + k8);
            #pragma unroll
            for (int nt = 0; nt < 4; nt++) {
                uint2 Bv = *(const uint2*)(FCb + (wn * 32 + nt * 8 + g) * 72 + k8);
                mma8(hacc[0][nt], A0.x, A1.x, A0.y, A1.y, Bv.x, Bv.y);
                mma8(hacc[1][nt], A2.x, A3.x, A2.y, A3.y, Bv.x, Bv.y);
            }
        }

        if (c == 3) {
            if (l < 2) {
                #pragma unroll
                for (int mt = 0; mt < 2; mt++)
                #pragma unroll
                for (int nt = 0; nt < 4; nt++) {
                    int o = wn * 32 + nt * 8;
                    int row = wm * 32 + mt * 16 + g;
                    float* h4 = hacc[mt][nt];
                    int a0 = row * 136 + o + pe;
                    int a1 = (row + 8) * 136 + o + pe;
                    Xu[a0]     = f2tf(h4[0] + tanh_fast(h4[0]));
                    Xu[a0 + 2] = f2tf(h4[1] + tanh_fast(h4[1]));
                    Xu[a1]     = f2tf(h4[2] + tanh_fast(h4[2]));
                    Xu[a1 + 2] = f2tf(h4[3] + tanh_fast(h4[3]));
                }
                bc[tid] = Wcf_b[(l + 1) * H_ + tid];
                bd[tid] = 128.f * Wdf_b[(l + 1) * H_ + tid];
                #pragma unroll
                for (int mt = 0; mt < 2; mt++)
                #pragma unroll
                for (int nt = 0; nt < 4; nt++)
                #pragma unroll
                for (int e = 0; e < 4; e++) hacc[mt][nt][e] = 0.f;
            } else {
                #pragma unroll
                for (int mt = 0; mt < 2; mt++)
                #pragma unroll
                for (int nt = 0; nt < 4; nt++) {
                    int col = wn * 32 + nt * 8 + 2 * t;
                    float* h4 = hacc[mt][nt];
                    pool += (h4[0] + tanh_fast(h4[0])) * vv[col];
                    pool += (h4[1] + tanh_fast(h4[1])) * vv[col + 1];
                    pool += (h4[2] + tanh_fast(h4[2])) * vv[col];
                    pool += (h4[3] + tanh_fast(h4[3])) * vv[col + 1];
                }
                rd[tid] = pool;
                __syncthreads();
                for (int s = 128; s > 0; s >>= 1) {
                    if (tid < s) rd[tid] += rd[tid + s];
                    __syncthreads();
                }
                if (tid == 0) atomicAdd(out + (blockIdx.x >> 1), rd[0]);
            }
        }
        if (i < 11) { __syncthreads(); }
    }
}

// ---------------- launch ----------------
extern "C" void kernel_launch(void* const* d_in, const int* in_sizes, int n_in,
                              void* d_out, int out_size) {
    const float* x     = (const float*)d_in[0];
    const float* dist  = (const float*)d_in[1];
    const float* Wcf_w = (const float*)d_in[2];
    const float* Wcf_b = (const float*)d_in[3];
    const float* Wdf_w = (const float*)d_in[4];
    const float* Wdf_b = (const float*)d_in[5];
    const float* Wfc_w = (const float*)d_in[6];
    const float* fc0_w = (const float*)d_in[7];
    const float* fc0_b = (const float*)d_in[8];
    const float* out_w = (const float*)d_in[9];
    const float* out_b = (const float*)d_in[10];
    float* out = (float*)d_out;

    cudaFuncSetAttribute(dtnn_mma_kernel,
                         cudaFuncAttributeMaxDynamicSharedMemorySize, SMEMB);

    prep_reduce_kernel<<<141 + ROWS, 256>>>(dist, x, Wcf_w, Wdf_w, Wfc_w,
                                            fc0_w, fc0_b, out_w, out_b, out);
    dtnn_mma_kernel<<<128, 256, SMEMB>>>(Wcf_b, Wdf_b, out);
}

// round 10
// speedup vs baseline: 1.1594x; 1.0231x over previous
#include <cuda_runtime.h>
#include <cstdint>

#define B_   64
#define N_   128
#define F_   128
#define R_   64
#define H_   256
#define L_   3
#define ROWS (B_*N_)

// image sizes in words (plain tf32 rows; strides 140 for K=128, 76 for K=64)
#define XSW 8960    // [64][140]
#define CFW 8960    // [64][140]
#define DSW 4864    // [64][76]
#define DFW 4864    // [64][76]
#define FCW 9728    // [128][76]

__device__ float4 g_cf[12 * CFW / 4];
__device__ float4 g_df[12 * DFW / 4];
__device__ float4 g_fc[12 * FCW / 4];
__device__ float4 g_xs[128 * XSW / 4];
__device__ float4 g_ds[128 * DSW / 4];
__device__ float g_v[F_];

__device__ __forceinline__ uint32_t f2tf(float x) {
    uint32_t r; asm("cvt.rna.tf32.f32 %0, %1;" : "=r"(r) : "f"(x)); return r;
}
__device__ __forceinline__ float tanh_fast(float x) {
    float r; asm("tanh.approx.f32 %0, %1;" : "=f"(r) : "f"(x)); return r;
}
__device__ __forceinline__ void mma8(float* d, uint32_t a0, uint32_t a1, uint32_t a2, uint32_t a3,
                                     uint32_t b0, uint32_t b1) {
    asm volatile(
        "mma.sync.aligned.m16n8k8.row.col.f32.tf32.tf32.f32 "
        "{%0,%1,%2,%3},{%4,%5,%6,%7},{%8,%9},{%0,%1,%2,%3};"
        : "+f"(d[0]), "+f"(d[1]), "+f"(d[2]), "+f"(d[3])
        : "r"(a0), "r"(a1), "r"(a2), "r"(a3), "r"(b0), "r"(b1));
}
#define LDSM4(r0,r1,r2,r3,addr) \
    asm volatile("ldmatrix.sync.aligned.m8n8.x4.shared.b16 {%0,%1,%2,%3}, [%4];" \
        : "=r"(r0), "=r"(r1), "=r"(r2), "=r"(r3) : "r"(addr))
__device__ __forceinline__ void cpa16(uint32_t dst, const float4* src) {
    asm volatile("cp.async.ca.shared.global [%0], [%1], 16;" :: "r"(dst), "l"(src));
}
#define CP_COMMIT() asm volatile("cp.async.commit_group;" ::: "memory")
template<int N>
__device__ __forceinline__ void cp_wait() {
    asm volatile("cp.async.wait_group %0;" :: "n"(N) : "memory");
}
template<int NC>
__device__ __forceinline__ void copy_img(uint32_t dst, const float4* __restrict__ src, int tid) {
    #pragma unroll
    for (int i = tid; i < NC; i += 256) cpa16(dst + i * 16, src + i);
}
__device__ __forceinline__ uint32_t smem_u32(const void* p) {
    uint32_t a;
    asm("{ .reg .u64 t; cvta.to.shared.u64 t, %1; cvt.u32.u64 %0, t; }" : "=r"(a) : "l"(p));
    return a;
}
// cvt a float4 -> tf32 uint4
__device__ __forceinline__ uint4 tf4(float4 v) {
    uint4 o; o.x = f2tf(v.x); o.y = f2tf(v.y); o.z = f2tf(v.z); o.w = f2tf(v.w); return o;
}

// ---------------- Kernel A: prep (141 blocks) + streaming reduce (8192 blocks) ----------------
__global__ void prep_reduce_kernel(const float* __restrict__ dist, const float* __restrict__ x,
                                   const float* __restrict__ Wcf_w, const float* __restrict__ Wdf_w,
                                   const float* __restrict__ Wfc_w,
                                   const float* __restrict__ fc0_w, const float* __restrict__ fc0_b,
                                   const float* __restrict__ out_w, const float* __restrict__ out_b,
                                   float* __restrict__ out) {
    int bid = blockIdx.x, tid = threadIdx.x;
    if (bid >= 141) {                      // ---- reduce one row (32KB) ----
        int row = bid - 141;
        const float4* p = (const float4*)(dist + (size_t)row * (N_ * R_));
        float4 acc = make_float4(0.f, 0.f, 0.f, 0.f);
        #pragma unroll
        for (int t = 0; t < 8; t++) {
            float4 v = __ldcs(&p[tid + t * 256]);
            acc.x += v.x; acc.y += v.y; acc.z += v.z; acc.w += v.w;
        }
        __shared__ float4 s[256];
        s[tid] = acc;
        __syncthreads();
        if (tid < 16) {
            float4 a = s[tid];
            #pragma unroll
            for (int m = 1; m < 16; m++) {
                float4 b = s[tid + 16 * m];
                a.x += b.x; a.y += b.y; a.z += b.z; a.w += b.w;
            }
            uint4* dp = (uint4*)((float*)g_ds + (row >> 6) * DSW + (row & 63) * 76 + tid * 4);
            *dp = tf4(a);
        }
    } else if (bid < 128) {                // ---- x tile image ----
        float* dst = (float*)g_xs + bid * XSW;
        const float* src = x + (size_t)bid * 64 * 128;
        #pragma unroll
        for (int i = 0; i < 8; i++) {
            int idx = tid + i * 256;                  // 2048 float4
            int row = idx >> 5, c4 = (idx & 31) * 4;
            *(uint4*)(dst + row * 140 + c4) = tf4(*(const float4*)(src + row * 128 + c4));
        }
    } else if (bid < 140) {                // ---- weight chunk images ----
        int wi = bid - 128, l = wi >> 2, c = wi & 3;
        float* dcf = (float*)g_cf + wi * CFW;
        const float* scf = Wcf_w + (size_t)l * 32768 + c * 8192;
        #pragma unroll
        for (int i = 0; i < 8; i++) {
            int idx = tid + i * 256;
            int row = idx >> 5, c4 = (idx & 31) * 4;
            *(uint4*)(dcf + row * 140 + c4) = tf4(*(const float4*)(scf + row * 128 + c4));
        }
        float* ddf = (float*)g_df + wi * DFW;
        const float* sdf = Wdf_w + (size_t)l * 16384 + c * 4096;
        #pragma unroll
        for (int i = 0; i < 4; i++) {
            int idx = tid + i * 256;                  // 1024 float4
            int row = idx >> 4, c4 = (idx & 15) * 4;
            *(uint4*)(ddf + row * 76 + c4) = tf4(*(const float4*)(sdf + row * 64 + c4));
        }
        float* dfc = (float*)g_fc + wi * FCW;
        const float* sfc = Wfc_w + (size_t)l * 32768 + c * 64;
        #pragma unroll
        for (int i = 0; i < 8; i++) {
            int idx = tid + i * 256;                  // 2048 float4
            int row = idx >> 4, c4 = (idx & 15) * 4;
            *(uint4*)(dfc + row * 76 + c4) = tf4(*(const float4*)(sfc + row * 256 + c4));
        }
    } else {                               // ---- fold head + init out ----
        if (tid < 128) {
            float a = 0.f;
            #pragma unroll 8
            for (int c = 0; c < 256; c++) a += out_w[c] * fc0_w[c * F_ + tid];
            g_v[tid] = a;
        }
        __shared__ float cs;
        if (tid == 0) {
            float s = out_b[0];
            for (int c = 0; c < 256; c++) s += out_w[c] * fc0_b[c];
            cs = s;
        }
        __syncthreads();
        if (tid < B_) out[tid] = cs;
    }
}

// ---------------- Kernel B: ldmatrix + mma.sync, fused 3 layers + pooling ----------------
enum {
    OXS  = 0,
    ODS  = OXS + XSW,     // 8960
    OPB  = ODS + DSW,     // 13824
    OCF0 = OPB + DSW,     // 18688
    OCF1 = OCF0 + CFW,    // 27648
    ODF0 = OCF1 + CFW,    // 36608
    ODF1 = ODF0 + DFW,    // 41472
    OFC  = ODF1 + DFW,    // 46336
    OBC  = OFC + FCW,     // 56064
    OBD  = OBC + 256,
    OVV  = OBD + 256,
    ORD  = OVV + 128,
    TOTW = ORD + 256      // 56960 words = 227840 B
};
#define SMEMB (TOTW * 4)

__global__ __launch_bounds__(256, 1)
void dtnn_mma_kernel(const float* __restrict__ Wcf_b, const float* __restrict__ Wdf_b,
                     float* __restrict__ out) {
    extern __shared__ float sm[];
    float* Xs = sm + OXS; float* Pb = sm + OPB;
    float* bc = sm + OBC; float* bd = sm + OBD;
    float* vv = sm + OVV; float* rd = sm + ORD;
    uint32_t sb = smem_u32(sm);

    int tid = threadIdx.x, lane = tid & 31, w = tid >> 5;
    int g = lane >> 2, t = lane & 3;
    int wm = w & 1, wn = w >> 1;          // warp grid: 2 (M) x 4 (N)
    int bid = blockIdx.x;

    // ldmatrix per-lane tile addressing: lrow = row-in-16, lchk = 0/16B (k 0-3 / 4-7)
    int lrow = (lane & 7) + ((lane >> 3) & 1) * 8;
    int lchk = ((lane >> 4) & 1) * 16;
    uint32_t aX0 = sb + (OXS + (wm * 32 + lrow) * 140) * 4 + lchk;
    uint32_t aX1 = aX0 + 16 * 140 * 4;
    uint32_t aD0 = sb + (ODS + (wm * 32 + lrow) * 76) * 4 + lchk;
    uint32_t aD1 = aD0 + 16 * 76 * 4;
    uint32_t aP0 = sb + (OPB + (wm * 32 + lrow) * 76) * 4 + lchk;
    uint32_t aP1 = aP0 + 16 * 76 * 4;
    uint32_t bF0 = sb + (OFC + (wn * 32 + lrow) * 76) * 4 + lchk;
    uint32_t bF1 = bF0 + 16 * 76 * 4;

    copy_img<XSW/4>(sb + OXS * 4, g_xs + bid * (XSW/4), tid);
    copy_img<DSW/4>(sb + ODS * 4, g_ds + bid * (DSW/4), tid);
    copy_img<CFW/4>(sb + OCF0 * 4, g_cf, tid);
    copy_img<DFW/4>(sb + ODF0 * 4, g_df, tid);
    CP_COMMIT();
    bc[tid] = Wcf_b[tid];
    bd[tid] = 128.f * Wdf_b[tid];
    if (tid < 128) vv[tid] = g_v[tid];
    cp_wait<0>();
    __syncthreads();

    float hacc[2][4][4] = {};
    float pool = 0.f;

    for (int i = 0; i < 12; i++) {
        int l = i >> 2, c = i & 3, buf = i & 1;

        copy_img<FCW/4>(sb + OFC * 4, g_fc + i * (FCW/4), tid);
        CP_COMMIT();
        if (i < 11) {
            copy_img<CFW/4>(sb + (buf ? OCF0 : OCF1) * 4, g_cf + (i + 1) * (CFW/4), tid);
            copy_img<DFW/4>(sb + (buf ? ODF0 : ODF1) * 4, g_df + (i + 1) * (DFW/4), tid);
            CP_COMMIT();
        }

        uint32_t bCF = sb + ((buf ? OCF1 : OCF0) + (wn * 16 + lrow) * 140) * 4 + lchk;
        uint32_t bDF = sb + ((buf ? ODF1 : ODF0) + (wn * 16 + lrow) * 76) * 4 + lchk;

        float cf[2][2][4] = {}, df[2][2][4] = {};
        #pragma unroll
        for (int ks = 0; ks < 16; ks++) {      // cf: Xs[64x128] @ CF^T
            uint32_t a0, a1, a2, a3, a4, a5, a6, a7, b0, b1, b2, b3;
            LDSM4(a0, a1, a2, a3, aX0 + ks * 32);
            LDSM4(a4, a5, a6, a7, aX1 + ks * 32);
            LDSM4(b0, b1, b2, b3, bCF + ks * 32);
            mma8(cf[0][0], a0, a1, a2, a3, b0, b2);
            mma8(cf[0][1], a0, a1, a2, a3, b1, b3);
            mma8(cf[1][0], a4, a5, a6, a7, b0, b2);
            mma8(cf[1][1], a4, a5, a6, a7, b1, b3);
        }
        #pragma unroll
        for (int ks = 0; ks < 8; ks++) {       // df: Ds[64x64] @ DF^T
            uint32_t a0, a1, a2, a3, a4, a5, a6, a7, b0, b1, b2, b3;
            LDSM4(a0, a1, a2, a3, aD0 + ks * 32);
            LDSM4(a4, a5, a6, a7, aD1 + ks * 32);
            LDSM4(b0, b1, b2, b3, bDF + ks * 32);
            mma8(df[0][0], a0, a1, a2, a3, b0, b2);
            mma8(df[0][1], a0, a1, a2, a3, b1, b3);
            mma8(df[1][0], a4, a5, a6, a7, b0, b2);
            mma8(df[1][1], a4, a5, a6, a7, b1, b3);
        }
        // P = (cf+bc)*(df+128*bd) -> Pb (plain tf32 rows)
        int hc = c * 64;
        #pragma unroll
        for (int mt = 0; mt < 2; mt++)
        #pragma unroll
        for (int nt = 0; nt < 2; nt++) {
            int col = wn * 16 + nt * 8 + 2 * t;
            int row = wm * 32 + mt * 16 + g;
            float b0c = bc[hc + col], b1c = bc[hc + col + 1];
            float b0d = bd[hc + col], b1d = bd[hc + col + 1];
            float* f4 = cf[mt][nt];
            float* d4 = df[mt][nt];
            float2 p01, p23;
            p01.x = __uint_as_float(f2tf((f4[0] + b0c) * (d4[0] + b0d)));
            p01.y = __uint_as_float(f2tf((f4[1] + b1c) * (d4[1] + b1d)));
            p23.x = __uint_as_float(f2tf((f4[2] + b0c) * (d4[2] + b0d)));
            p23.y = __uint_as_float(f2tf((f4[3] + b1c) * (d4[3] + b1d)));
            *(float2*)(Pb + row * 76 + col) = p01;
            *(float2*)(Pb + (row + 8) * 76 + col) = p23;
        }

        if (i < 11) cp_wait<1>(); else cp_wait<0>();   // FC[i] arrived
        __syncthreads();

        #pragma unroll
        for (int ks = 0; ks < 8; ks++) {       // fc: Pb[64x64] @ FC^T (accumulate)
            uint32_t p0, p1, p2, p3, p4, p5, p6, p7, b0, b1, b2, b3, c0, c1, c2, c3;
            LDSM4(p0, p1, p2, p3, aP0 + ks * 32);
            LDSM4(p4, p5, p6, p7, aP1 + ks * 32);
            LDSM4(b0, b1, b2, b3, bF0 + ks * 32);
            LDSM4(c0, c1, c2, c3, bF1 + ks * 32);
            mma8(hacc[0][0], p0, p1, p2, p3, b0, b2);
            mma8(hacc[0][1], p0, p1, p2, p3, b1, b3);
            mma8(hacc[0][2], p0, p1, p2, p3, c0, c2);
            mma8(hacc[0][3], p0, p1, p2, p3, c1, c3);
            mma8(hacc[1][0], p4, p5, p6, p7, b0, b2);
            mma8(hacc[1][1], p4, p5, p6, p7, b1, b3);
            mma8(hacc[1][2], p4, p5, p6, p7, c0, c2);
            mma8(hacc[1][3], p4, p5, p6, p7, c1, c3);
        }

        if (c == 3) {
            if (l < 2) {
                #pragma unroll
                for (int mt = 0; mt < 2; mt++)
                #pragma unroll
                for (int nt = 0; nt < 4; nt++) {
                    int col = wn * 32 + nt * 8 + 2 * t;
                    int row = wm * 32 + mt * 16 + g;
                    float* h4 = hacc[mt][nt];
                    float2 x01, x23;
                    x01.x = __uint_as_float(f2tf(h4[0] + tanh_fast(h4[0])));
                    x01.y = __uint_as_float(f2tf(h4[1] + tanh_fast(h4[1])));
                    x23.x = __uint_as_float(f2tf(h4[2] + tanh_fast(h4[2])));
                    x23.y = __uint_as_float(f2tf(h4[3] + tanh_fast(h4[3])));
                    *(float2*)(Xs + row * 140 + col) = x01;
                    *(float2*)(Xs + (row + 8) * 140 + col) = x23;
                }
                bc[tid] = Wcf_b[(l + 1) * H_ + tid];
                bd[tid] = 128.f * Wdf_b[(l + 1) * H_ + tid];
                #pragma unroll
                for (int mt = 0; mt < 2; mt++)
                #pragma unroll
                for (int nt = 0; nt < 4; nt++)
                #pragma unroll
                for (int e = 0; e < 4; e++) hacc[mt][nt][e] = 0.f;
            } else {
                #pragma unroll
                for (int mt = 0; mt < 2; mt++)
                #pragma unroll
                for (int nt = 0; nt < 4; nt++) {
                    int col = wn * 32 + nt * 8 + 2 * t;
                    float* h4 = hacc[mt][nt];
                    pool += (h4[0] + tanh_fast(h4[0])) * vv[col];
                    pool += (h4[1] + tanh_fast(h4[1])) * vv[col + 1];
                    pool += (h4[2] + tanh_fast(h4[2])) * vv[col];
                    pool += (h4[3] + tanh_fast(h4[3])) * vv[col + 1];
                }
                rd[tid] = pool;
                __syncthreads();
                for (int s = 128; s > 0; s >>= 1) {
                    if (tid < s) rd[tid] += rd[tid + s];
                    __syncthreads();
                }
                if (tid == 0) atomicAdd(out + (blockIdx.x >> 1), rd[0]);
            }
        }
        if (i < 11) { __syncthreads(); }
    }
}

// ---------------- launch ----------------
extern "C" void kernel_launch(void* const* d_in, const int* in_sizes, int n_in,
                              void* d_out, int out_size) {
    const float* x     = (const float*)d_in[0];
    const float* dist  = (const float*)d_in[1];
    const float* Wcf_w = (const float*)d_in[2];
    const float* Wcf_b = (const float*)d_in[3];
    const float* Wdf_w = (const float*)d_in[4];
    const float* Wdf_b = (const float*)d_in[5];
    const float* Wfc_w = (const float*)d_in[6];
    const float* fc0_w = (const float*)d_in[7];
    const float* fc0_b = (const float*)d_in[8];
    const float* out_w = (const float*)d_in[9];
    const float* out_b = (const float*)d_in[10];
    float* out = (float*)d_out;

    cudaFuncSetAttribute(dtnn_mma_kernel,
                         cudaFuncAttributeMaxDynamicSharedMemorySize, SMEMB);

    prep_reduce_kernel<<<141 + ROWS, 256>>>(dist, x, Wcf_w, Wdf_w, Wfc_w,
                                            fc0_w, fc0_b, out_w, out_b, out);
    dtnn_mma_kernel<<<128, 256, SMEMB>>>(Wcf_b, Wdf_b, out);
}

// round 11
// speedup vs baseline: 1.5496x; 1.3365x over previous
#include <cuda_runtime.h>
#include <cuda_fp16.h>
#include <cstdint>

#define B_   64
#define N_   128
#define F_   128
#define R_   64
#define H_   256
#define L_   3
#define ROWS (B_*N_)

// half images: row strides 136 halves (K=128), 72 halves (K=64)
// byte sizes:
#define XSB 17408   // 64*136*2
#define CFB 17408
#define DSB 9216    // 64*72*2
#define DFB 9216
#define FCB 18432   // 128*72*2

__device__ uint4 g_cf[12 * CFB / 16];
__device__ uint4 g_df[12 * DFB / 16];
__device__ uint4 g_fc[12 * FCB / 16];
__device__ uint4 g_xs[128 * XSB / 16];
__device__ uint4 g_ds[128 * DSB / 16];
__device__ float g_v[F_];

__device__ __forceinline__ float tanh_fast(float x) {
    float r; asm("tanh.approx.f32 %0, %1;" : "=f"(r) : "f"(x)); return r;
}
__device__ __forceinline__ uint32_t f2h2(float lo, float hi) {
    __half2 h = __floats2half2_rn(lo, hi);
    return *(uint32_t*)&h;
}
__device__ __forceinline__ void mma16(float* d, uint32_t a0, uint32_t a1, uint32_t a2, uint32_t a3,
                                      uint32_t b0, uint32_t b1) {
    asm volatile(
        "mma.sync.aligned.m16n8k16.row.col.f32.f16.f16.f32 "
        "{%0,%1,%2,%3},{%4,%5,%6,%7},{%8,%9},{%0,%1,%2,%3};"
        : "+f"(d[0]), "+f"(d[1]), "+f"(d[2]), "+f"(d[3])
        : "r"(a0), "r"(a1), "r"(a2), "r"(a3), "r"(b0), "r"(b1));
}
#define LDSM4(r0,r1,r2,r3,addr) \
    asm volatile("ldmatrix.sync.aligned.m8n8.x4.shared.b16 {%0,%1,%2,%3}, [%4];" \
        : "=r"(r0), "=r"(r1), "=r"(r2), "=r"(r3) : "r"(addr))
__device__ __forceinline__ void cpa16(uint32_t dst, const uint4* src) {
    asm volatile("cp.async.ca.shared.global [%0], [%1], 16;" :: "r"(dst), "l"(src));
}
#define CP_COMMIT() asm volatile("cp.async.commit_group;" ::: "memory")
template<int N>
__device__ __forceinline__ void cp_wait() {
    asm volatile("cp.async.wait_group %0;" :: "n"(N) : "memory");
}
template<int NC>
__device__ __forceinline__ void copy_img(uint32_t dst, const uint4* __restrict__ src, int tid) {
    #pragma unroll
    for (int i = tid; i < NC; i += 256) cpa16(dst + i * 16, src + i);
}
__device__ __forceinline__ uint32_t smem_u32(const void* p) {
    uint32_t a;
    asm("{ .reg .u64 t; cvta.to.shared.u64 t, %1; cvt.u32.u64 %0, t; }" : "=r"(a) : "l"(p));
    return a;
}
// pack 8 consecutive fp32 -> 8 fp16 (uint4)
__device__ __forceinline__ void pack8(char* dst, const float* __restrict__ src) {
    float4 a = *(const float4*)src;
    float4 b = *(const float4*)(src + 4);
    uint4 o;
    o.x = f2h2(a.x, a.y); o.y = f2h2(a.z, a.w);
    o.z = f2h2(b.x, b.y); o.w = f2h2(b.z, b.w);
    *(uint4*)dst = o;
}

// ---------------- Kernel A: prep (141 blocks) + streaming reduce (8192 blocks) ----------------
__global__ void prep_reduce_kernel(const float* __restrict__ dist, const float* __restrict__ x,
                                   const float* __restrict__ Wcf_w, const float* __restrict__ Wdf_w,
                                   const float* __restrict__ Wfc_w,
                                   const float* __restrict__ fc0_w, const float* __restrict__ fc0_b,
                                   const float* __restrict__ out_w, const float* __restrict__ out_b,
                                   float* __restrict__ out) {
    int bid = blockIdx.x, tid = threadIdx.x;
    if (bid >= 141) {                      // ---- reduce one row (32KB) ----
        int row = bid - 141;
        const float4* p = (const float4*)(dist + (size_t)row * (N_ * R_));
        float4 acc = make_float4(0.f, 0.f, 0.f, 0.f);
        #pragma unroll
        for (int t = 0; t < 8; t++) {
            float4 v = __ldcs(&p[tid + t * 256]);
            acc.x += v.x; acc.y += v.y; acc.z += v.z; acc.w += v.w;
        }
        __shared__ float4 s[256];
        s[tid] = acc;
        __syncthreads();
        if (tid < 16) {
            float4 a = s[tid];
            #pragma unroll
            for (int m = 1; m < 16; m++) {
                float4 b = s[tid + 16 * m];
                a.x += b.x; a.y += b.y; a.z += b.z; a.w += b.w;
            }
            char* dp = (char*)g_ds + (row >> 6) * DSB + (row & 63) * 144 + tid * 8;
            uint2 o; o.x = f2h2(a.x, a.y); o.y = f2h2(a.z, a.w);
            *(uint2*)dp = o;
        }
    } else if (bid < 128) {                // ---- x tile image ----
        char* dst = (char*)g_xs + (size_t)bid * XSB;
        const float* src = x + (size_t)bid * 64 * 128;
        #pragma unroll
        for (int i = 0; i < 4; i++) {      // 1024 octets
            int oct = tid + i * 256;
            int row = oct >> 4, ko = oct & 15;
            pack8(dst + row * 272 + ko * 16, src + row * 128 + ko * 8);
        }
    } else if (bid < 140) {                // ---- weight chunk images ----
        int wi = bid - 128, l = wi >> 2, c = wi & 3;
        char* dcf = (char*)g_cf + (size_t)wi * CFB;
        const float* scf = Wcf_w + (size_t)l * 32768 + c * 8192;
        #pragma unroll
        for (int i = 0; i < 4; i++) {      // 1024 octets
            int oct = tid + i * 256;
            int row = oct >> 4, ko = oct & 15;
            pack8(dcf + row * 272 + ko * 16, scf + row * 128 + ko * 8);
        }
        char* ddf = (char*)g_df + (size_t)wi * DFB;
        const float* sdf = Wdf_w + (size_t)l * 16384 + c * 4096;
        #pragma unroll
        for (int i = 0; i < 2; i++) {      // 512 octets
            int oct = tid + i * 256;
            int row = oct >> 3, ko = oct & 7;
            pack8(ddf + row * 144 + ko * 16, sdf + row * 64 + ko * 8);
        }
        char* dfc = (char*)g_fc + (size_t)wi * FCB;
        const float* sfc = Wfc_w + (size_t)l * 32768 + c * 64;
        #pragma unroll
        for (int i = 0; i < 4; i++) {      // 1024 octets
            int oct = tid + i * 256;
            int row = oct >> 3, ko = oct & 7;
            pack8(dfc + row * 144 + ko * 16, sfc + row * 256 + ko * 8);
        }
    } else {                               // ---- fold head + init out ----
        if (tid < 128) {
            float a = 0.f;
            #pragma unroll 8
            for (int c = 0; c < 256; c++) a += out_w[c] * fc0_w[c * F_ + tid];
            g_v[tid] = a;
        }
        __shared__ float cs;
        if (tid == 0) {
            float s = out_b[0];
            for (int c = 0; c < 256; c++) s += out_w[c] * fc0_b[c];
            cs = s;
        }
        __syncthreads();
        if (tid < B_) out[tid] = cs;
    }
}

// ---------------- Kernel B: fp16 ldmatrix + mma, fused 3 layers + pooling ----------------
// byte offsets into dynamic smem
enum {
    OXS  = 0,
    ODS  = OXS + XSB,     // 17408
    OPB  = ODS + DSB,     // 26624
    OCF0 = OPB + DSB,     // 35840
    OCF1 = OCF0 + CFB,    // 53248
    ODF0 = OCF1 + CFB,    // 70656
    ODF1 = ODF0 + DFB,    // 79872
    OFC  = ODF1 + DFB,    // 89088
    OBC  = OFC + FCB,     // 107520
    OBD  = OBC + 1024,
    OVV  = OBD + 1024,
    ORD  = OVV + 512,
    SMEMB = ORD + 1024    // 111616 B
};

__global__ __launch_bounds__(256, 1)
void dtnn_mma_kernel(const float* __restrict__ Wcf_b, const float* __restrict__ Wdf_b,
                     float* __restrict__ out) {
    extern __shared__ char smc[];
    float* bc = (float*)(smc + OBC);
    float* bd = (float*)(smc + OBD);
    float* vv = (float*)(smc + OVV);
    float* rd = (float*)(smc + ORD);
    __half2* Ph = (__half2*)(smc + OPB);
    __half2* Xh = (__half2*)(smc + OXS);
    uint32_t sb = smem_u32(smc);

    int tid = threadIdx.x, lane = tid & 31, w = tid >> 5;
    int g = lane >> 2, t = lane & 3;
    int wm = w & 1, wn = w >> 1;          // warp grid: 2 (M) x 4 (N)
    int bid = blockIdx.x;

    // ldmatrix lane addressing: lrow = row in 16-tile, lchk = 0/16B (k 0-7 / 8-15 halves)
    int lrow = (lane & 7) + ((lane >> 3) & 1) * 8;
    int lchk = ((lane >> 4) & 1) * 16;
    uint32_t aX0 = sb + OXS + (wm * 32 + lrow) * 272 + lchk;
    uint32_t aX1 = aX0 + 16 * 272;
    uint32_t aD0 = sb + ODS + (wm * 32 + lrow) * 144 + lchk;
    uint32_t aD1 = aD0 + 16 * 144;
    uint32_t aP0 = sb + OPB + (wm * 32 + lrow) * 144 + lchk;
    uint32_t aP1 = aP0 + 16 * 144;
    uint32_t bF0 = sb + OFC + (wn * 32 + lrow) * 144 + lchk;
    uint32_t bF1 = bF0 + 16 * 144;

    copy_img<XSB/16>(sb + OXS, g_xs + bid * (XSB/16), tid);
    copy_img<DSB/16>(sb + ODS, g_ds + bid * (DSB/16), tid);
    copy_img<CFB/16>(sb + OCF0, g_cf, tid);
    copy_img<DFB/16>(sb + ODF0, g_df, tid);
    CP_COMMIT();
    bc[tid] = Wcf_b[tid];
    bd[tid] = 128.f * Wdf_b[tid];
    if (tid < 128) vv[tid] = g_v[tid];
    cp_wait<0>();
    __syncthreads();

    float hacc[2][4][4] = {};
    float pool = 0.f;

    for (int i = 0; i < 12; i++) {
        int l = i >> 2, c = i & 3, buf = i & 1;

        copy_img<FCB/16>(sb + OFC, g_fc + i * (FCB/16), tid);
        CP_COMMIT();
        if (i < 11) {
            copy_img<CFB/16>(sb + (buf ? OCF0 : OCF1), g_cf + (i + 1) * (CFB/16), tid);
            copy_img<DFB/16>(sb + (buf ? ODF0 : ODF1), g_df + (i + 1) * (DFB/16), tid);
            CP_COMMIT();
        }

        uint32_t bCF = sb + (buf ? OCF1 : OCF0) + (wn * 16 + lrow) * 272 + lchk;
        uint32_t bDF = sb + (buf ? ODF1 : ODF0) + (wn * 16 + lrow) * 144 + lchk;

        float cf[2][2][4] = {}, df[2][2][4] = {};
        #pragma unroll
        for (int ks = 0; ks < 8; ks++) {       // cf: Xs[64x128] @ CF^T (K=16 per step)
            uint32_t a0, a1, a2, a3, a4, a5, a6, a7, b0, b1, b2, b3;
            LDSM4(a0, a1, a2, a3, aX0 + ks * 32);
            LDSM4(a4, a5, a6, a7, aX1 + ks * 32);
            LDSM4(b0, b1, b2, b3, bCF + ks * 32);
            mma16(cf[0][0], a0, a1, a2, a3, b0, b2);
            mma16(cf[0][1], a0, a1, a2, a3, b1, b3);
            mma16(cf[1][0], a4, a5, a6, a7, b0, b2);
            mma16(cf[1][1], a4, a5, a6, a7, b1, b3);
        }
        #pragma unroll
        for (int ks = 0; ks < 4; ks++) {       // df: Ds[64x64] @ DF^T
            uint32_t a0, a1, a2, a3, a4, a5, a6, a7, b0, b1, b2, b3;
            LDSM4(a0, a1, a2, a3, aD0 + ks * 32);
            LDSM4(a4, a5, a6, a7, aD1 + ks * 32);
            LDSM4(b0, b1, b2, b3, bDF + ks * 32);
            mma16(df[0][0], a0, a1, a2, a3, b0, b2);
            mma16(df[0][1], a0, a1, a2, a3, b1, b3);
            mma16(df[1][0], a4, a5, a6, a7, b0, b2);
            mma16(df[1][1], a4, a5, a6, a7, b1, b3);
        }
        // P = (cf+bc)*(df+128*bd) -> Pb (fp16)
        int hc = c * 64;
        #pragma unroll
        for (int mt = 0; mt < 2; mt++)
        #pragma unroll
        for (int nt = 0; nt < 2; nt++) {
            int col = wn * 16 + nt * 8 + 2 * t;
            int row = wm * 32 + mt * 16 + g;
            float b0c = bc[hc + col], b1c = bc[hc + col + 1];
            float b0d = bd[hc + col], b1d = bd[hc + col + 1];
            float* f4 = cf[mt][nt];
            float* d4 = df[mt][nt];
            Ph[(row * 72 + col) >> 1] =
                __floats2half2_rn((f4[0] + b0c) * (d4[0] + b0d), (f4[1] + b1c) * (d4[1] + b1d));
            Ph[((row + 8) * 72 + col) >> 1] =
                __floats2half2_rn((f4[2] + b0c) * (d4[2] + b0d), (f4[3] + b1c) * (d4[3] + b1d));
        }

        if (i < 11) cp_wait<1>(); else cp_wait<0>();   // FC[i] arrived
        __syncthreads();

        #pragma unroll
        for (int ks = 0; ks < 4; ks++) {       // fc: Pb[64x64] @ FC^T (accumulate)
            uint32_t p0, p1, p2, p3, p4, p5, p6, p7, b0, b1, b2, b3, c0, c1, c2, c3;
            LDSM4(p0, p1, p2, p3, aP0 + ks * 32);
            LDSM4(p4, p5, p6, p7, aP1 + ks * 32);
            LDSM4(b0, b1, b2, b3, bF0 + ks * 32);
            LDSM4(c0, c1, c2, c3, bF1 + ks * 32);
            mma16(hacc[0][0], p0, p1, p2, p3, b0, b2);
            mma16(hacc[0][1], p0, p1, p2, p3, b1, b3);
            mma16(hacc[0][2], p0, p1, p2, p3, c0, c2);
            mma16(hacc[0][3], p0, p1, p2, p3, c1, c3);
            mma16(hacc[1][0], p4, p5, p6, p7, b0, b2);
            mma16(hacc[1][1], p4, p5, p6, p7, b1, b3);
            mma16(hacc[1][2], p4, p5, p6, p7, c0, c2);
            mma16(hacc[1][3], p4, p5, p6, p7, c1, c3);
        }

        if (c == 3) {
            if (l < 2) {
                #pragma unroll
                for (int mt = 0; mt < 2; mt++)
                #pragma unroll
                for (int nt = 0; nt < 4; nt++) {
                    int col = wn * 32 + nt * 8 + 2 * t;
                    int row = wm * 32 + mt * 16 + g;
                    float* h4 = hacc[mt][nt];
                    Xh[(row * 136 + col) >> 1] =
                        __floats2half2_rn(h4[0] + tanh_fast(h4[0]), h4[1] + tanh_fast(h4[1]));
                    Xh[((row + 8) * 136 + col) >> 1] =
                        __floats2half2_rn(h4[2] + tanh_fast(h4[2]), h4[3] + tanh_fast(h4[3]));
                }
                bc[tid] = Wcf_b[(l + 1) * H_ + tid];
                bd[tid] = 128.f * Wdf_b[(l + 1) * H_ + tid];
                #pragma unroll
                for (int mt = 0; mt < 2; mt++)
                #pragma unroll
                for (int nt = 0; nt < 4; nt++)
                #pragma unroll
                for (int e = 0; e < 4; e++) hacc[mt][nt][e] = 0.f;
            } else {
                #pragma unroll
                for (int mt = 0; mt < 2; mt++)
                #pragma unroll
                for (int nt = 0; nt < 4; nt++) {
                    int col = wn * 32 + nt * 8 + 2 * t;
                    float* h4 = hacc[mt][nt];
                    pool += (h4[0] + tanh_fast(h4[0])) * vv[col];
                    pool += (h4[1] + tanh_fast(h4[1])) * vv[col + 1];
                    pool += (h4[2] + tanh_fast(h4[2])) * vv[col];
                    pool += (h4[3] + tanh_fast(h4[3])) * vv[col + 1];
                }
                rd[tid] = pool;
                __syncthreads();
                for (int s = 128; s > 0; s >>= 1) {
                    if (tid < s) rd[tid] += rd[tid + s];
                    __syncthreads();
                }
                if (tid == 0) atomicAdd(out + (blockIdx.x >> 1), rd[0]);
            }
        }
        if (i < 11) { __syncthreads(); }
    }
}

// ---------------- launch ----------------
extern "C" void kernel_launch(void* const* d_in, const int* in_sizes, int n_in,
                              void* d_out, int out_size) {
    const float* x     = (const float*)d_in[0];
    const float* dist  = (const float*)d_in[1];
    const float* Wcf_w = (const float*)d_in[2];
    const float* Wcf_b = (const float*)d_in[3];
    const float* Wdf_w = (const float*)d_in[4];
    const float* Wdf_b = (const float*)d_in[5];
    const float* Wfc_w = (const float*)d_in[6];
    const float* fc0_w = (const float*)d_in[7];
    const float* fc0_b = (const float*)d_in[8];
    const float* out_w = (const float*)d_in[9];
    const float* out_b = (const float*)d_in[10];
    float* out = (float*)d_out;

    cudaFuncSetAttribute(dtnn_mma_kernel,
                         cudaFuncAttributeMaxDynamicSharedMemorySize, SMEMB);

    prep_reduce_kernel<<<141 + ROWS, 256>>>(dist, x, Wcf_w, Wdf_w, Wfc_w,
                                            fc0_w, fc0_b, out_w, out_b, out);
    dtnn_mma_kernel<<<128, 256, SMEMB>>>(Wcf_b, Wdf_b, out);
}